// round 5
// baseline (speedup 1.0000x reference)
#include <cuda_runtime.h>

#define SQ   2048
#define DIM  768
#define NH   12
#define HDIM 64
#define MROWS 8192      // B*S
#define HALF 384        // DIM/2

// ---------------- scratch (device globals; no allocations) ----------------
__device__ float g_Q[MROWS * DIM];
__device__ float g_K[MROWS * DIM];
__device__ float g_V[MROWS * DIM];
__device__ float g_A[MROWS * DIM];
__device__ float g_cos[SQ * HALF];
__device__ float g_sin[SQ * HALF];

// ---------------- f32x2 helpers (Blackwell packed fp32) ----------------
__device__ __forceinline__ unsigned long long pk2(float x) {
    unsigned long long r;
    asm("mov.b64 %0, {%1, %1};" : "=l"(r) : "f"(x));
    return r;
}
__device__ __forceinline__ void fma2(unsigned long long& d, unsigned long long a, unsigned long long b) {
    asm("fma.rn.f32x2 %0, %1, %2, %0;" : "+l"(d) : "l"(a), "l"(b));
}
__device__ __forceinline__ float2 upk(unsigned long long v) {
    float2 f;
    asm("mov.b64 {%0, %1}, %2;" : "=f"(f.x), "=f"(f.y) : "l"(v));
    return f;
}
__device__ __forceinline__ unsigned long long mul2(unsigned long long a, unsigned long long b) {
    unsigned long long r;
    asm("mul.rn.f32x2 %0, %1, %2;" : "=l"(r) : "l"(a), "l"(b));
    return r;
}

// ---------------- RoPE table ----------------
__global__ void rope_table_kernel() {
    int idx = blockIdx.x * blockDim.x + threadIdx.x;
    if (idx >= SQ * HALF) return;
    int s = idx / HALF;
    int i = idx - s * HALF;
    float e = (2.0f * (float)i) / 768.0f;
    float invf = 1.0f / powf(10000.0f, e);
    float ang = (float)s * invf;
    float sv, cv;
    sincosf(ang, &sv, &cv);
    g_cos[idx] = cv;
    g_sin[idx] = sv;
}

// ---------------- SGEMM core: C[8192,768] = A @ W + bias (opt. RoPE) ----------------
// BM=BN=128, BK=16, 256 threads, 8x8 micro-tile, f32x2 accumulators.
// Double-buffered smem with register prefetch: one __syncthreads per K-iter,
// global loads for tile kt+1 issued before compute on tile kt.
__device__ __forceinline__ void gemm_core(
    const float* __restrict__ A, const float* __restrict__ W,
    const float* __restrict__ bias, float* __restrict__ C, bool doRope)
{
    __shared__ float As[2][16 * 132];  // transposed [k][m], pad 132
    __shared__ float Bs[2][16 * 128];  // [k][n]

    int tid = threadIdx.x;
    int ty = tid >> 4, tx = tid & 15;
    int row0 = blockIdx.y * 128;
    int col0 = blockIdx.x * 128;

    unsigned long long acc[8][4];
#pragma unroll
    for (int i = 0; i < 8; i++)
#pragma unroll
        for (int j = 0; j < 4; j++) acc[i][j] = 0ULL;

    int aRow = tid >> 2;        // 0..63
    int aCol = (tid & 3) * 4;   // 0..12
    int bRow = tid >> 5;        // 0..7
    int bCol = (tid & 31) * 4;  // 0..124

    const float* aPtr0 = &A[(row0 + aRow) * DIM + aCol];
    const float* aPtr1 = &A[(row0 + aRow + 64) * DIM + aCol];
    const float* bPtr0 = &W[bRow * DIM + col0 + bCol];
    const float* bPtr1 = &W[(bRow + 8) * DIM + col0 + bCol];

    float4 pa0, pa1, pb0, pb1;

    // preload tile 0 -> regs -> smem buf 0
    pa0 = *(const float4*)(aPtr0);
    pa1 = *(const float4*)(aPtr1);
    pb0 = *(const float4*)(bPtr0);
    pb1 = *(const float4*)(bPtr1);
    {
        float t0[4] = {pa0.x, pa0.y, pa0.z, pa0.w};
        float t1[4] = {pa1.x, pa1.y, pa1.z, pa1.w};
#pragma unroll
        for (int c = 0; c < 4; c++) {
            As[0][(aCol + c) * 132 + aRow]      = t0[c];
            As[0][(aCol + c) * 132 + aRow + 64] = t1[c];
        }
        *(float4*)&Bs[0][bRow * 128 + bCol]       = pb0;
        *(float4*)&Bs[0][(bRow + 8) * 128 + bCol] = pb1;
    }
    __syncthreads();

    for (int kt = 0; kt < 48; kt++) {
        int cur = kt & 1;

        // prefetch tile kt+1 into registers (overlaps with compute below)
        if (kt < 47) {
            int ko = (kt + 1) * 16;
            pa0 = *(const float4*)(aPtr0 + ko);
            pa1 = *(const float4*)(aPtr1 + ko);
            pb0 = *(const float4*)(bPtr0 + ko * DIM);
            pb1 = *(const float4*)(bPtr1 + ko * DIM);
        }

        // compute on buffer cur
#pragma unroll
        for (int k = 0; k < 16; k++) {
            float4 a0 = *(const float4*)&As[cur][k * 132 + ty * 8];
            float4 a1 = *(const float4*)&As[cur][k * 132 + ty * 8 + 4];
            ulonglong2 bb0 = *(const ulonglong2*)&Bs[cur][k * 128 + tx * 8];
            ulonglong2 bb1 = *(const ulonglong2*)&Bs[cur][k * 128 + tx * 8 + 4];
            float av[8] = {a0.x, a0.y, a0.z, a0.w, a1.x, a1.y, a1.z, a1.w};
#pragma unroll
            for (int i = 0; i < 8; i++) {
                unsigned long long ap = pk2(av[i]);
                fma2(acc[i][0], ap, bb0.x);
                fma2(acc[i][1], ap, bb0.y);
                fma2(acc[i][2], ap, bb1.x);
                fma2(acc[i][3], ap, bb1.y);
            }
        }

        // store prefetched tile into the other buffer, single barrier
        if (kt < 47) {
            int nxt = cur ^ 1;
            float t0[4] = {pa0.x, pa0.y, pa0.z, pa0.w};
            float t1[4] = {pa1.x, pa1.y, pa1.z, pa1.w};
#pragma unroll
            for (int c = 0; c < 4; c++) {
                As[nxt][(aCol + c) * 132 + aRow]      = t0[c];
                As[nxt][(aCol + c) * 132 + aRow + 64] = t1[c];
            }
            *(float4*)&Bs[nxt][bRow * 128 + bCol]       = pb0;
            *(float4*)&Bs[nxt][(bRow + 8) * 128 + bCol] = pb1;
            __syncthreads();
        }
    }

    int crow0 = row0 + ty * 8;
    int ccol0 = col0 + tx * 8;
#pragma unroll
    for (int i = 0; i < 8; i++) {
        int row = crow0 + i;
        int s = row & (SQ - 1);
        float out[8];
#pragma unroll
        for (int j2 = 0; j2 < 4; j2++) {
            float2 v = upk(acc[i][j2]);
            int ce = ccol0 + 2 * j2;          // even global column
            v.x += bias[ce];
            v.y += bias[ce + 1];
            if (doRope) {
                int hi = ce >> 1;
                float cv = g_cos[s * HALF + hi];
                float sv = g_sin[s * HALF + hi];
                float r1 = v.x * cv - v.y * sv;
                float r2 = v.x * sv + v.y * cv;
                v.x = r1; v.y = r2;
            }
            out[2 * j2] = v.x;
            out[2 * j2 + 1] = v.y;
        }
        *(float4*)&C[row * DIM + ccol0]     = make_float4(out[0], out[1], out[2], out[3]);
        *(float4*)&C[row * DIM + ccol0 + 4] = make_float4(out[4], out[5], out[6], out[7]);
    }
}

__global__ void __launch_bounds__(256) gemm_qkv_kernel(
    const float* __restrict__ X,
    const float* __restrict__ Wq, const float* __restrict__ Wk, const float* __restrict__ Wv,
    const float* __restrict__ bq, const float* __restrict__ bk, const float* __restrict__ bv)
{
    int z = blockIdx.z;
    const float* W = (z == 0) ? Wq : ((z == 1) ? Wk : Wv);
    const float* b = (z == 0) ? bq : ((z == 1) ? bk : bv);
    float* C = (z == 0) ? g_Q : ((z == 1) ? g_K : g_V);
    gemm_core(X, W, b, C, z < 2);
}

__global__ void __launch_bounds__(256) gemm_out_kernel(
    const float* __restrict__ Wo, const float* __restrict__ bo, float* __restrict__ out)
{
    gemm_core(g_A, Wo, bo, out, false);
}

// ---------------- causal flash attention, 64-row Q tiles ----------------
// Thread map: ty=tid/16 owns rows 4ty..4ty+3, tx=tid%16 owns cols/dims 4tx..4tx+3.
// K stored transposed [d][c] with chunk-XOR swizzle; P tile aliases the K buffer.
// qt reversed vs blockIdx.x so heaviest CTAs are scheduled first (tail balance).
__global__ void __launch_bounds__(256) attn_kernel() {
    __shared__ float Qs[64 * 64];
    __shared__ float KP[64 * 64];   // K (transposed, swizzled) then P (plain)
    __shared__ float Vs[64 * 64];

    int tid = threadIdx.x;
    int ty = tid >> 4, tx = tid & 15;
    int qt = (SQ / 64 - 1) - blockIdx.x;   // heavy tiles first
    int bh = blockIdx.y;
    int b = bh / NH, h = bh - b * NH;
    int qrow0 = qt * 64;

    int lr = tid >> 4;          // 0..15 (loader row)
    int ld = (tid & 15) * 4;    // 0..60 (loader dim)

    // load Q tile, pre-scaled by 1/sqrt(hd)=0.125 (exact power of two)
#pragma unroll
    for (int p = 0; p < 4; p++) {
        int r = p * 16 + lr;
        float4 qv = *(const float4*)&g_Q[(b * SQ + qrow0 + r) * DIM + h * HDIM + ld];
        qv.x *= 0.125f; qv.y *= 0.125f; qv.z *= 0.125f; qv.w *= 0.125f;
        *(float4*)&Qs[r * 64 + ld] = qv;
    }

    float m[4], l[4];
    unsigned long long o2[4][2];
#pragma unroll
    for (int i = 0; i < 4; i++) { m[i] = -1e30f; l[i] = 0.0f; o2[i][0] = 0ULL; o2[i][1] = 0ULL; }
    __syncthreads();

    for (int kt = 0; kt <= qt; kt++) {
        int krow0 = kt * 64;
        // load K transposed+swizzled, V natural
#pragma unroll
        for (int p = 0; p < 4; p++) {
            int c = p * 16 + lr;
            float4 kv = *(const float4*)&g_K[(b * SQ + krow0 + c) * DIM + h * HDIM + ld];
            float tmpk[4] = {kv.x, kv.y, kv.z, kv.w};
#pragma unroll
            for (int j = 0; j < 4; j++) {
                int d = ld + j;
                KP[d * 64 + ((((c >> 2) ^ (d >> 2)) & 15) << 2) + (c & 3)] = tmpk[j];
            }
            *(float4*)&Vs[c * 64 + ld] =
                *(const float4*)&g_V[(b * SQ + krow0 + c) * DIM + h * HDIM + ld];
        }
        __syncthreads();

        // scores: acc2[i][jp] = rows 4ty+i x col-pairs (4tx+2jp, 4tx+2jp+1)
        unsigned long long acc2[4][2];
#pragma unroll
        for (int i = 0; i < 4; i++) { acc2[i][0] = 0ULL; acc2[i][1] = 0ULL; }
#pragma unroll
        for (int d4 = 0; d4 < 16; d4++) {
            float qa[4][4];
#pragma unroll
            for (int i = 0; i < 4; i++) {
                float4 q4 = *(const float4*)&Qs[(4 * ty + i) * 64 + 4 * d4];
                qa[i][0] = q4.x; qa[i][1] = q4.y; qa[i][2] = q4.z; qa[i][3] = q4.w;
            }
            int chunk = ((tx ^ d4) & 15) << 2;   // physical chunk holding logical cols 4tx..
#pragma unroll
            for (int dd = 0; dd < 4; dd++) {
                int d = 4 * d4 + dd;
                ulonglong2 kk = *(const ulonglong2*)&KP[d * 64 + chunk];
#pragma unroll
                for (int i = 0; i < 4; i++) {
                    unsigned long long ap = pk2(qa[i][dd]);
                    fma2(acc2[i][0], ap, kk.x);
                    fma2(acc2[i][1], ap, kk.y);
                }
            }
        }
        __syncthreads();   // all done reading K before overwriting KP with P

        // online softmax update
        float pr[4][4];
#pragma unroll
        for (int i = 0; i < 4; i++) {
            float2 v0 = upk(acc2[i][0]);
            float2 v1 = upk(acc2[i][1]);
            float sc[4] = {v0.x, v0.y, v1.x, v1.y};
            int rowg = qrow0 + 4 * ty + i;
#pragma unroll
            for (int j = 0; j < 4; j++) {
                int colg = krow0 + 4 * tx + j;
                if (colg > rowg) sc[j] = -1e30f;       // causal mask
            }
            float mx = fmaxf(fmaxf(sc[0], sc[1]), fmaxf(sc[2], sc[3]));
#pragma unroll
            for (int o = 8; o > 0; o >>= 1) mx = fmaxf(mx, __shfl_xor_sync(0xffffffffu, mx, o));
            float mn = fmaxf(m[i], mx);
            float scale = __expf(m[i] - mn);
            float rs = 0.0f;
#pragma unroll
            for (int j = 0; j < 4; j++) {
                float p = __expf(sc[j] - mn);
                pr[i][j] = p;
                rs += p;
            }
#pragma unroll
            for (int o = 8; o > 0; o >>= 1) rs += __shfl_xor_sync(0xffffffffu, rs, o);
            l[i] = l[i] * scale + rs;
            m[i] = mn;
            unsigned long long s2 = pk2(scale);
            o2[i][0] = mul2(o2[i][0], s2);
            o2[i][1] = mul2(o2[i][1], s2);
        }
#pragma unroll
        for (int i = 0; i < 4; i++)
            *(float4*)&KP[(4 * ty + i) * 64 + 4 * tx] =
                make_float4(pr[i][0], pr[i][1], pr[i][2], pr[i][3]);
        __syncthreads();   // P visible

        // PV: o2[i][jp] += P[row][k] * V[k][dim-pair]
#pragma unroll
        for (int k4 = 0; k4 < 16; k4++) {
            float pa[4][4];
#pragma unroll
            for (int i = 0; i < 4; i++) {
                float4 pv = *(const float4*)&KP[(4 * ty + i) * 64 + 4 * k4];
                pa[i][0] = pv.x; pa[i][1] = pv.y; pa[i][2] = pv.z; pa[i][3] = pv.w;
            }
#pragma unroll
            for (int kk2 = 0; kk2 < 4; kk2++) {
                ulonglong2 v2 = *(const ulonglong2*)&Vs[(4 * k4 + kk2) * 64 + 4 * tx];
#pragma unroll
                for (int i = 0; i < 4; i++) {
                    unsigned long long pp = pk2(pa[i][kk2]);
                    fma2(o2[i][0], pp, v2.x);
                    fma2(o2[i][1], pp, v2.y);
                }
            }
        }
        __syncthreads();   // done reading P/V before next tile load
    }

    // epilogue: normalize and write
#pragma unroll
    for (int i = 0; i < 4; i++) {
        float inv = 1.0f / l[i];
        float2 a = upk(o2[i][0]);
        float2 c = upk(o2[i][1]);
        *(float4*)&g_A[(b * SQ + qrow0 + 4 * ty + i) * DIM + h * HDIM + 4 * tx] =
            make_float4(a.x * inv, a.y * inv, c.x * inv, c.y * inv);
    }
}

// ---------------- launch ----------------
extern "C" void kernel_launch(void* const* d_in, const int* in_sizes, int n_in,
                              void* d_out, int out_size) {
    const float* X  = (const float*)d_in[0];
    const float* Wq = (const float*)d_in[1];
    const float* bq = (const float*)d_in[2];
    const float* Wk = (const float*)d_in[3];
    const float* bk = (const float*)d_in[4];
    const float* Wv = (const float*)d_in[5];
    const float* bv = (const float*)d_in[6];
    const float* Wo = (const float*)d_in[7];
    const float* bo = (const float*)d_in[8];
    float* out = (float*)d_out;

    rope_table_kernel<<<(SQ * HALF + 255) / 256, 256>>>();
    gemm_qkv_kernel<<<dim3(6, 64, 3), 256>>>(X, Wq, Wk, Wv, bq, bk, bv);
    attn_kernel<<<dim3(32, 48), 256>>>();
    gemm_out_kernel<<<dim3(6, 64), 256>>>(Wo, bo, out);
}

// round 11
// speedup vs baseline: 1.4009x; 1.4009x over previous
#include <cuda_runtime.h>
#include <cuda_bf16.h>
#include <cstdint>

#define SQ   2048
#define DIM  768
#define NH   12
#define HDIM 64
#define MROWS 8192      // B*S
#define HALF 384        // DIM/2

// ---------------- scratch (device globals; no allocations) ----------------
__device__ float g_Q[MROWS * DIM];
__device__ float g_K[MROWS * DIM];
__device__ float g_V[MROWS * DIM];
__device__ float g_A[MROWS * DIM];
__device__ float g_cos[SQ * HALF];
__device__ float g_sin[SQ * HALF];
// bf16 hi/lo splits
__device__ __nv_bfloat16 g_Xhi[MROWS * DIM];
__device__ __nv_bfloat16 g_Xlo[MROWS * DIM];
__device__ __nv_bfloat16 g_Ahi[MROWS * DIM];
__device__ __nv_bfloat16 g_Alo[MROWS * DIM];
// transposed weights [n][k], 4 matrices (q,k,v,o)
__device__ __nv_bfloat16 g_Wthi[4 * DIM * DIM];
__device__ __nv_bfloat16 g_Wtlo[4 * DIM * DIM];

// ---------------- f32x2 helpers (attention) ----------------
__device__ __forceinline__ unsigned long long pk2(float x) {
    unsigned long long r;
    asm("mov.b64 %0, {%1, %1};" : "=l"(r) : "f"(x));
    return r;
}
__device__ __forceinline__ void fma2(unsigned long long& d, unsigned long long a, unsigned long long b) {
    asm("fma.rn.f32x2 %0, %1, %2, %0;" : "+l"(d) : "l"(a), "l"(b));
}
__device__ __forceinline__ float2 upk(unsigned long long v) {
    float2 f;
    asm("mov.b64 {%0, %1}, %2;" : "=f"(f.x), "=f"(f.y) : "l"(v));
    return f;
}
__device__ __forceinline__ unsigned long long mul2(unsigned long long a, unsigned long long b) {
    unsigned long long r;
    asm("mul.rn.f32x2 %0, %1, %2;" : "=l"(r) : "l"(a), "l"(b));
    return r;
}

// ---------------- HMMA helpers (base sm_103 target: mma.sync + ldmatrix + cp.async) ----------------
__device__ __forceinline__ uint32_t smem_u32(const void* p) {
    uint32_t a;
    asm("{ .reg .u64 t; cvta.to.shared.u64 t, %1; cvt.u32.u64 %0, t; }" : "=r"(a) : "l"(p));
    return a;
}
#define SWZ(off) ((off) ^ (((off) >> 3) & 0x70))

__device__ __forceinline__ void ldsm4(uint32_t* r, uint32_t addr) {
    asm volatile("ldmatrix.sync.aligned.m8n8.x4.shared.b16 {%0,%1,%2,%3}, [%4];"
                 : "=r"(r[0]), "=r"(r[1]), "=r"(r[2]), "=r"(r[3]) : "r"(addr));
}
__device__ __forceinline__ void mma16816(float* d, const uint32_t* a, const uint32_t* b) {
    asm volatile(
        "mma.sync.aligned.m16n8k16.row.col.f32.bf16.bf16.f32 "
        "{%0,%1,%2,%3}, {%4,%5,%6,%7}, {%8,%9}, {%0,%1,%2,%3};"
        : "+f"(d[0]), "+f"(d[1]), "+f"(d[2]), "+f"(d[3])
        : "r"(a[0]), "r"(a[1]), "r"(a[2]), "r"(a[3]), "r"(b[0]), "r"(b[1]));
}
__device__ __forceinline__ void cp16(uint32_t dst, const void* src) {
    asm volatile("cp.async.cg.shared.global [%0], [%1], 16;" :: "r"(dst), "l"(src));
}

// ---------------- RoPE table ----------------
__global__ void rope_table_kernel() {
    int idx = blockIdx.x * blockDim.x + threadIdx.x;
    if (idx >= SQ * HALF) return;
    int s = idx / HALF;
    int i = idx - s * HALF;
    float e = (2.0f * (float)i) / 768.0f;
    float invf = 1.0f / powf(10000.0f, e);
    float ang = (float)s * invf;
    float sv, cv;
    sincosf(ang, &sv, &cv);
    g_cos[idx] = cv;
    g_sin[idx] = sv;
}

// ---------------- fp32 -> bf16 hi/lo split ----------------
// dst_sel 0: src_param (harness X) -> g_Xhi/g_Xlo
// dst_sel 1: g_A (device symbol, resolved in DEVICE code) -> g_Ahi/g_Alo
__global__ void split_kernel(const float* __restrict__ src_param, int dst_sel) {
    const float* src = dst_sel ? (const float*)g_A : src_param;
    __nv_bfloat16* hi = dst_sel ? g_Ahi : g_Xhi;
    __nv_bfloat16* lo = dst_sel ? g_Alo : g_Xlo;
    int i4 = blockIdx.x * blockDim.x + threadIdx.x;
    if (i4 * 4 >= MROWS * DIM) return;
    float4 v = *(const float4*)&src[i4 * 4];
    float vv[4] = {v.x, v.y, v.z, v.w};
    __nv_bfloat16 h[4], l[4];
#pragma unroll
    for (int j = 0; j < 4; j++) {
        h[j] = __float2bfloat16(vv[j]);
        l[j] = __float2bfloat16(vv[j] - __bfloat162float(h[j]));
    }
    *(uint2*)&hi[i4 * 4] = *(uint2*)h;
    *(uint2*)&lo[i4 * 4] = *(uint2*)l;
}

// ---------------- transpose + split weights: Wt[n][k] = W[k][n] ----------------
__global__ void wsplit_kernel(const float* __restrict__ W0, const float* __restrict__ W1,
                              const float* __restrict__ W2, const float* __restrict__ W3) {
    __shared__ float t[32][33];
    int z = blockIdx.z;
    const float* W = (z == 0) ? W0 : ((z == 1) ? W1 : ((z == 2) ? W2 : W3));
    int k0 = blockIdx.x * 32;
    int n0 = blockIdx.y * 32;
    int tx = threadIdx.x, ty = threadIdx.y;
#pragma unroll
    for (int i = 0; i < 4; i++) {
        int ry = ty + i * 8;
        t[ry][tx] = W[(k0 + ry) * DIM + n0 + tx];
    }
    __syncthreads();
    size_t base = (size_t)z * DIM * DIM;
#pragma unroll
    for (int i = 0; i < 4; i++) {
        int n = n0 + ty + i * 8;
        int k = k0 + tx;
        float v = t[tx][ty + i * 8];
        __nv_bfloat16 h = __float2bfloat16(v);
        __nv_bfloat16 l = __float2bfloat16(v - __bfloat162float(h));
        g_Wthi[base + (size_t)n * DIM + k] = h;
        g_Wtlo[base + (size_t)n * DIM + k] = l;
    }
}

// ---------------- HMMA bf16-split GEMM: C[8192,768] = A @ W + bias (opt RoPE) ----------------
// CTA tile 128x64, 8 warps 4(M)x2(N), warp tile 32x32, k-chunk = 32 real k.
// Smem row = 64 bf16 = 128B: cols [0:32)=hi, [32:64)=lo, XOR swizzle.
// Products per chunk: hh (a0b0,a1b1), hl (a0b2,a1b3), lh (a2b0,a3b1); lo*lo dropped.
__device__ __forceinline__ void hgemm_core(
    const __nv_bfloat16* __restrict__ Ahi, const __nv_bfloat16* __restrict__ Alo,
    const __nv_bfloat16* __restrict__ Bhi, const __nv_bfloat16* __restrict__ Blo,
    const float* __restrict__ bias, float* __restrict__ C, bool doRope)
{
    __shared__ __align__(128) char Asm[2][16384];   // 128 rows x 128B
    __shared__ __align__(128) char Bsm[2][8192];    // 64 rows x 128B

    int tid = threadIdx.x;
    int lane = tid & 31, wid = tid >> 5;
    int wm = wid & 3, wn = wid >> 2;
    int row0 = blockIdx.y * 128;
    int col0 = blockIdx.x * 64;

    uint32_t aBase = smem_u32(Asm);
    uint32_t bBase = smem_u32(Bsm);

    float acc[2][4][4];
#pragma unroll
    for (int i = 0; i < 2; i++)
#pragma unroll
        for (int j = 0; j < 4; j++)
#pragma unroll
            for (int q = 0; q < 4; q++) acc[i][j][q] = 0.0f;

    // cp.async fill of one stage for chunk kt (1536 x 16B: 1024 A + 512 B)
    auto issue = [&](int st, int kt) {
#pragma unroll
        for (int i = 0; i < 6; i++) {
            int idx = tid + i * 256;
            if (idx < 1024) {
                int row = idx >> 3, c16 = idx & 7;
                const __nv_bfloat16* s = (c16 < 4) ? Ahi : Alo;
                const void* src = s + (size_t)(row0 + row) * DIM + kt * 32 + (c16 & 3) * 8;
                cp16(aBase + st * 16384 + SWZ((uint32_t)(row * 128 + c16 * 16)), src);
            } else {
                int j = idx - 1024;
                int row = j >> 3, c16 = j & 7;
                const __nv_bfloat16* s = (c16 < 4) ? Bhi : Blo;
                const void* src = s + (size_t)(col0 + row) * DIM + kt * 32 + (c16 & 3) * 8;
                cp16(bBase + st * 8192 + SWZ((uint32_t)(row * 128 + c16 * 16)), src);
            }
        }
    };

    issue(0, 0);
    asm volatile("cp.async.commit_group;" ::: "memory");

    for (int kt = 0; kt < 24; kt++) {
        int st = kt & 1;
        if (kt < 23) {
            issue(st ^ 1, kt + 1);
            asm volatile("cp.async.commit_group;" ::: "memory");
            asm volatile("cp.async.wait_group 1;" ::: "memory");
        } else {
            asm volatile("cp.async.wait_group 0;" ::: "memory");
        }
        __syncthreads();

        uint32_t aTile = aBase + st * 16384;
        uint32_t bTile = bBase + st * 8192;

        // preload all 4 a-steps (k16 steps: 0,1=hi; 2,3=lo), 2 m-frags each
        uint32_t af[4][2][4];
        int arow = wm * 32 + (lane & 15);
        int abyte = ((lane >> 4) & 1) * 16;
#pragma unroll
        for (int s2 = 0; s2 < 4; s2++)
#pragma unroll
            for (int mf = 0; mf < 2; mf++)
                ldsm4(af[s2][mf], aTile + SWZ((uint32_t)((arow + mf * 16) * 128 + abyte + s2 * 32)));

        // stream b-steps; products per b-step: b0:{a0,a2} b1:{a1,a3} b2:{a0} b3:{a1}
        const int alist[4][2] = {{0, 2}, {1, 3}, {0, -1}, {1, -1}};
        int brow_base = wn * 32 + ((lane >> 4) & 1) * 8 + (lane & 7);
        int bbyte = ((lane >> 3) & 1) * 16;
#pragma unroll
        for (int s2 = 0; s2 < 4; s2++) {
            uint32_t bfr[2][4];
#pragma unroll
            for (int np = 0; np < 2; np++)
                ldsm4(bfr[np], bTile + SWZ((uint32_t)((brow_base + np * 16) * 128 + bbyte + s2 * 32)));
#pragma unroll
            for (int q = 0; q < 2; q++) {
                int a = alist[s2][q];
                if (a >= 0) {
#pragma unroll
                    for (int mf = 0; mf < 2; mf++)
#pragma unroll
                        for (int np = 0; np < 2; np++) {
                            mma16816(acc[mf][np * 2 + 0], af[a][mf], &bfr[np][0]);
                            mma16816(acc[mf][np * 2 + 1], af[a][mf], &bfr[np][2]);
                        }
                }
            }
        }
        __syncthreads();   // all smem reads done before next issue overwrites this stage
    }

    // epilogue: thread t of warp owns rows (wm*32+mf*16+t/4, +8), cols (wn*32+nf*8+2*(t%4), +1)
#pragma unroll
    for (int mf = 0; mf < 2; mf++) {
#pragma unroll
        for (int nf = 0; nf < 4; nf++) {
            int cg = col0 + wn * 32 + nf * 8 + 2 * (lane & 3);
            float b0 = bias[cg], b1 = bias[cg + 1];
            int hi = cg >> 1;
#pragma unroll
            for (int half = 0; half < 2; half++) {
                int row = row0 + wm * 32 + mf * 16 + (lane >> 2) + half * 8;
                float v0 = acc[mf][nf][half * 2 + 0] + b0;
                float v1 = acc[mf][nf][half * 2 + 1] + b1;
                if (doRope) {
                    int s = row & (SQ - 1);
                    float cv = g_cos[s * HALF + hi];
                    float sv = g_sin[s * HALF + hi];
                    float r1 = v0 * cv - v1 * sv;
                    float r2 = v0 * sv + v1 * cv;
                    v0 = r1; v1 = r2;
                }
                *(float2*)&C[(size_t)row * DIM + cg] = make_float2(v0, v1);
            }
        }
    }
}

__global__ void __launch_bounds__(256) hgemm_qkv_kernel(
    const float* __restrict__ bq, const float* __restrict__ bk, const float* __restrict__ bv)
{
    int z = blockIdx.z;
    const float* b = (z == 0) ? bq : ((z == 1) ? bk : bv);
    float* C = (z == 0) ? g_Q : ((z == 1) ? g_K : g_V);
    size_t wb = (size_t)z * DIM * DIM;
    hgemm_core(g_Xhi, g_Xlo, g_Wthi + wb, g_Wtlo + wb, b, C, z < 2);
}

__global__ void __launch_bounds__(256) hgemm_out_kernel(
    const float* __restrict__ bo, float* __restrict__ out)
{
    size_t wb = (size_t)3 * DIM * DIM;
    hgemm_core(g_Ahi, g_Alo, g_Wthi + wb, g_Wtlo + wb, bo, out, false);
}

// ---------------- causal flash attention, 64-row Q tiles (unchanged, passing) ----------------
__global__ void __launch_bounds__(256) attn_kernel() {
    __shared__ float Qs[64 * 64];
    __shared__ float KP[64 * 64];
    __shared__ float Vs[64 * 64];

    int tid = threadIdx.x;
    int ty = tid >> 4, tx = tid & 15;
    int qt = (SQ / 64 - 1) - blockIdx.x;   // heavy tiles first
    int bh = blockIdx.y;
    int b = bh / NH, h = bh - b * NH;
    int qrow0 = qt * 64;

    int lr = tid >> 4;
    int ld = (tid & 15) * 4;

#pragma unroll
    for (int p = 0; p < 4; p++) {
        int r = p * 16 + lr;
        float4 qv = *(const float4*)&g_Q[(b * SQ + qrow0 + r) * DIM + h * HDIM + ld];
        qv.x *= 0.125f; qv.y *= 0.125f; qv.z *= 0.125f; qv.w *= 0.125f;
        *(float4*)&Qs[r * 64 + ld] = qv;
    }

    float m[4], l[4];
    unsigned long long o2[4][2];
#pragma unroll
    for (int i = 0; i < 4; i++) { m[i] = -1e30f; l[i] = 0.0f; o2[i][0] = 0ULL; o2[i][1] = 0ULL; }
    __syncthreads();

    for (int kt = 0; kt <= qt; kt++) {
        int krow0 = kt * 64;
#pragma unroll
        for (int p = 0; p < 4; p++) {
            int c = p * 16 + lr;
            float4 kv = *(const float4*)&g_K[(b * SQ + krow0 + c) * DIM + h * HDIM + ld];
            float tmpk[4] = {kv.x, kv.y, kv.z, kv.w};
#pragma unroll
            for (int j = 0; j < 4; j++) {
                int d = ld + j;
                KP[d * 64 + ((((c >> 2) ^ (d >> 2)) & 15) << 2) + (c & 3)] = tmpk[j];
            }
            *(float4*)&Vs[c * 64 + ld] =
                *(const float4*)&g_V[(b * SQ + krow0 + c) * DIM + h * HDIM + ld];
        }
        __syncthreads();

        unsigned long long acc2[4][2];
#pragma unroll
        for (int i = 0; i < 4; i++) { acc2[i][0] = 0ULL; acc2[i][1] = 0ULL; }
#pragma unroll
        for (int d4 = 0; d4 < 16; d4++) {
            float qa[4][4];
#pragma unroll
            for (int i = 0; i < 4; i++) {
                float4 q4 = *(const float4*)&Qs[(4 * ty + i) * 64 + 4 * d4];
                qa[i][0] = q4.x; qa[i][1] = q4.y; qa[i][2] = q4.z; qa[i][3] = q4.w;
            }
            int chunk = ((tx ^ d4) & 15) << 2;
#pragma unroll
            for (int dd = 0; dd < 4; dd++) {
                int d = 4 * d4 + dd;
                ulonglong2 kk = *(const ulonglong2*)&KP[d * 64 + chunk];
#pragma unroll
                for (int i = 0; i < 4; i++) {
                    unsigned long long ap = pk2(qa[i][dd]);
                    fma2(acc2[i][0], ap, kk.x);
                    fma2(acc2[i][1], ap, kk.y);
                }
            }
        }
        __syncthreads();

        float pr[4][4];
#pragma unroll
        for (int i = 0; i < 4; i++) {
            float2 v0 = upk(acc2[i][0]);
            float2 v1 = upk(acc2[i][1]);
            float sc[4] = {v0.x, v0.y, v1.x, v1.y};
            int rowg = qrow0 + 4 * ty + i;
#pragma unroll
            for (int j = 0; j < 4; j++) {
                int colg = krow0 + 4 * tx + j;
                if (colg > rowg) sc[j] = -1e30f;
            }
            float mx = fmaxf(fmaxf(sc[0], sc[1]), fmaxf(sc[2], sc[3]));
#pragma unroll
            for (int o = 8; o > 0; o >>= 1) mx = fmaxf(mx, __shfl_xor_sync(0xffffffffu, mx, o));
            float mn = fmaxf(m[i], mx);
            float scale = __expf(m[i] - mn);
            float rs = 0.0f;
#pragma unroll
            for (int j = 0; j < 4; j++) {
                float p = __expf(sc[j] - mn);
                pr[i][j] = p;
                rs += p;
            }
#pragma unroll
            for (int o = 8; o > 0; o >>= 1) rs += __shfl_xor_sync(0xffffffffu, rs, o);
            l[i] = l[i] * scale + rs;
            m[i] = mn;
            unsigned long long s2 = pk2(scale);
            o2[i][0] = mul2(o2[i][0], s2);
            o2[i][1] = mul2(o2[i][1], s2);
        }
#pragma unroll
        for (int i = 0; i < 4; i++)
            *(float4*)&KP[(4 * ty + i) * 64 + 4 * tx] =
                make_float4(pr[i][0], pr[i][1], pr[i][2], pr[i][3]);
        __syncthreads();

#pragma unroll
        for (int k4 = 0; k4 < 16; k4++) {
            float pa[4][4];
#pragma unroll
            for (int i = 0; i < 4; i++) {
                float4 pv = *(const float4*)&KP[(4 * ty + i) * 64 + 4 * k4];
                pa[i][0] = pv.x; pa[i][1] = pv.y; pa[i][2] = pv.z; pa[i][3] = pv.w;
            }
#pragma unroll
            for (int kk2 = 0; kk2 < 4; kk2++) {
                ulonglong2 v2 = *(const ulonglong2*)&Vs[(4 * k4 + kk2) * 64 + 4 * tx];
#pragma unroll
                for (int i = 0; i < 4; i++) {
                    unsigned long long pp = pk2(pa[i][kk2]);
                    fma2(o2[i][0], pp, v2.x);
                    fma2(o2[i][1], pp, v2.y);
                }
            }
        }
        __syncthreads();
    }

#pragma unroll
    for (int i = 0; i < 4; i++) {
        float inv = 1.0f / l[i];
        float2 a = upk(o2[i][0]);
        float2 c = upk(o2[i][1]);
        *(float4*)&g_A[(b * SQ + qrow0 + 4 * ty + i) * DIM + h * HDIM + 4 * tx] =
            make_float4(a.x * inv, a.y * inv, c.x * inv, c.y * inv);
    }
}

// ---------------- launch ----------------
extern "C" void kernel_launch(void* const* d_in, const int* in_sizes, int n_in,
                              void* d_out, int out_size) {
    const float* X  = (const float*)d_in[0];
    const float* Wq = (const float*)d_in[1];
    const float* bq = (const float*)d_in[2];
    const float* Wk = (const float*)d_in[3];
    const float* bk = (const float*)d_in[4];
    const float* Wv = (const float*)d_in[5];
    const float* bv = (const float*)d_in[6];
    const float* Wo = (const float*)d_in[7];
    const float* bo = (const float*)d_in[8];
    float* out = (float*)d_out;

    rope_table_kernel<<<(SQ * HALF + 255) / 256, 256>>>();
    split_kernel<<<(MROWS * DIM / 4 + 255) / 256, 256>>>(X, 0);
    wsplit_kernel<<<dim3(24, 24, 4), dim3(32, 8)>>>(Wq, Wk, Wv, Wo);
    hgemm_qkv_kernel<<<dim3(12, 64, 3), 256>>>(bq, bk, bv);
    attn_kernel<<<dim3(32, 48), 256>>>();
    split_kernel<<<(MROWS * DIM / 4 + 255) / 256, 256>>>(X, 1);   // src ignored; reads g_A in device code
    hgemm_out_kernel<<<dim3(12, 64), 256>>>(bo, out);
}

// round 15
// speedup vs baseline: 2.0757x; 1.4817x over previous
#include <cuda_runtime.h>
#include <cuda_bf16.h>
#include <cstdint>

#define SQ   2048
#define DIM  768
#define NH   12
#define HDIM 64
#define MROWS 8192      // B*S
#define HALF 384        // DIM/2

// ---------------- scratch (device globals; no allocations) ----------------
__device__ float g_Q[MROWS * DIM];
__device__ float g_K[MROWS * DIM];
__device__ float g_V[MROWS * DIM];
__device__ float g_A[MROWS * DIM];
__device__ float g_cos[SQ * HALF];
__device__ float g_sin[SQ * HALF];
// bf16 hi/lo splits
__device__ __nv_bfloat16 g_Xhi[MROWS * DIM];
__device__ __nv_bfloat16 g_Xlo[MROWS * DIM];
__device__ __nv_bfloat16 g_Ahi[MROWS * DIM];
__device__ __nv_bfloat16 g_Alo[MROWS * DIM];
__device__ __nv_bfloat16 g_Qhi[MROWS * DIM];
__device__ __nv_bfloat16 g_Qlo[MROWS * DIM];
__device__ __nv_bfloat16 g_Khi[MROWS * DIM];
__device__ __nv_bfloat16 g_Klo[MROWS * DIM];
__device__ __nv_bfloat16 g_Vthi[MROWS * DIM];   // [b][dcol][c] = [(b*DIM+dcol)*SQ + c]
__device__ __nv_bfloat16 g_Vtlo[MROWS * DIM];
// transposed weights [n][k], 4 matrices (q,k,v,o)
__device__ __nv_bfloat16 g_Wthi[4 * DIM * DIM];
__device__ __nv_bfloat16 g_Wtlo[4 * DIM * DIM];

// ---------------- HMMA helpers (base sm_103 target) ----------------
__device__ __forceinline__ uint32_t smem_u32(const void* p) {
    uint32_t a;
    asm("{ .reg .u64 t; cvta.to.shared.u64 t, %1; cvt.u32.u64 %0, t; }" : "=r"(a) : "l"(p));
    return a;
}
#define SWZ(off) ((off) ^ (((off) >> 3) & 0x70))

__device__ __forceinline__ void ldsm4(uint32_t* r, uint32_t addr) {
    asm volatile("ldmatrix.sync.aligned.m8n8.x4.shared.b16 {%0,%1,%2,%3}, [%4];"
                 : "=r"(r[0]), "=r"(r[1]), "=r"(r[2]), "=r"(r[3]) : "r"(addr));
}
__device__ __forceinline__ void mma16816(float* d, const uint32_t* a, const uint32_t* b) {
    asm volatile(
        "mma.sync.aligned.m16n8k16.row.col.f32.bf16.bf16.f32 "
        "{%0,%1,%2,%3}, {%4,%5,%6,%7}, {%8,%9}, {%0,%1,%2,%3};"
        : "+f"(d[0]), "+f"(d[1]), "+f"(d[2]), "+f"(d[3])
        : "r"(a[0]), "r"(a[1]), "r"(a[2]), "r"(a[3]), "r"(b[0]), "r"(b[1]));
}
__device__ __forceinline__ void cp16(uint32_t dst, const void* src) {
    asm volatile("cp.async.cg.shared.global [%0], [%1], 16;" :: "r"(dst), "l"(src));
}
__device__ __forceinline__ uint32_t cvtpack(float hi, float lo) {
    uint32_t r;
    asm("cvt.rn.bf16x2.f32 %0, %1, %2;" : "=r"(r) : "f"(hi), "f"(lo));
    return r;
}

// ---------------- RoPE table ----------------
__global__ void rope_table_kernel() {
    int idx = blockIdx.x * blockDim.x + threadIdx.x;
    if (idx >= SQ * HALF) return;
    int s = idx / HALF;
    int i = idx - s * HALF;
    float e = (2.0f * (float)i) / 768.0f;
    float invf = 1.0f / powf(10000.0f, e);
    float ang = (float)s * invf;
    float sv, cv;
    sincosf(ang, &sv, &cv);
    g_cos[idx] = cv;
    g_sin[idx] = sv;
}

// ---------------- fp32 -> bf16 hi/lo split ----------------
// sel 0: src_param(X)->Xhi/lo   1: g_A->Ahi/lo   2: g_Q->Qhi/lo (x0.125)   3: g_K->Khi/lo
__global__ void split_kernel(const float* __restrict__ src_param, int sel) {
    const float* src;
    __nv_bfloat16 *hi, *lo;
    float scale = 1.0f;
    if (sel == 0)      { src = src_param;        hi = g_Xhi; lo = g_Xlo; }
    else if (sel == 1) { src = (const float*)g_A; hi = g_Ahi; lo = g_Alo; }
    else if (sel == 2) { src = (const float*)g_Q; hi = g_Qhi; lo = g_Qlo; scale = 0.125f; }
    else               { src = (const float*)g_K; hi = g_Khi; lo = g_Klo; }
    int i4 = blockIdx.x * blockDim.x + threadIdx.x;
    if (i4 * 4 >= MROWS * DIM) return;
    float4 v = *(const float4*)&src[i4 * 4];
    float vv[4] = {v.x * scale, v.y * scale, v.z * scale, v.w * scale};
    __nv_bfloat16 h[4], l[4];
#pragma unroll
    for (int j = 0; j < 4; j++) {
        h[j] = __float2bfloat16(vv[j]);
        l[j] = __float2bfloat16(vv[j] - __bfloat162float(h[j]));
    }
    *(uint2*)&hi[i4 * 4] = *(uint2*)h;
    *(uint2*)&lo[i4 * 4] = *(uint2*)l;
}

// ---------------- V transpose + split: g_V[b][c][dcol] -> g_Vt{hi,lo}[(b*DIM+dcol)*SQ+c] ----------------
__global__ void vtsplit_kernel() {
    __shared__ float t[32][33];
    int c0 = blockIdx.x * 32, d0 = blockIdx.y * 32, b = blockIdx.z;
    int tx = threadIdx.x, ty = threadIdx.y;
#pragma unroll
    for (int i = 0; i < 4; i++)
        t[ty + i * 8][tx] = g_V[(size_t)(b * SQ + c0 + ty + i * 8) * DIM + d0 + tx];
    __syncthreads();
#pragma unroll
    for (int i = 0; i < 4; i++) {
        int dl = ty + i * 8;
        float v = t[tx][dl];
        __nv_bfloat16 h = __float2bfloat16(v);
        __nv_bfloat16 l = __float2bfloat16(v - __bfloat162float(h));
        size_t off = (size_t)(b * DIM + d0 + dl) * SQ + c0 + tx;
        g_Vthi[off] = h;
        g_Vtlo[off] = l;
    }
}

// ---------------- transpose + split weights: Wt[n][k] = W[k][n] ----------------
__global__ void wsplit_kernel(const float* __restrict__ W0, const float* __restrict__ W1,
                              const float* __restrict__ W2, const float* __restrict__ W3) {
    __shared__ float t[32][33];
    int z = blockIdx.z;
    const float* W = (z == 0) ? W0 : ((z == 1) ? W1 : ((z == 2) ? W2 : W3));
    int k0 = blockIdx.x * 32;
    int n0 = blockIdx.y * 32;
    int tx = threadIdx.x, ty = threadIdx.y;
#pragma unroll
    for (int i = 0; i < 4; i++) {
        int ry = ty + i * 8;
        t[ry][tx] = W[(k0 + ry) * DIM + n0 + tx];
    }
    __syncthreads();
    size_t base = (size_t)z * DIM * DIM;
#pragma unroll
    for (int i = 0; i < 4; i++) {
        int n = n0 + ty + i * 8;
        int k = k0 + tx;
        float v = t[tx][ty + i * 8];
        __nv_bfloat16 h = __float2bfloat16(v);
        __nv_bfloat16 l = __float2bfloat16(v - __bfloat162float(h));
        g_Wthi[base + (size_t)n * DIM + k] = h;
        g_Wtlo[base + (size_t)n * DIM + k] = l;
    }
}

// ---------------- HMMA bf16-split GEMM (unchanged from passing R11) ----------------
__device__ __forceinline__ void hgemm_core(
    const __nv_bfloat16* __restrict__ Ahi, const __nv_bfloat16* __restrict__ Alo,
    const __nv_bfloat16* __restrict__ Bhi, const __nv_bfloat16* __restrict__ Blo,
    const float* __restrict__ bias, float* __restrict__ C, bool doRope)
{
    __shared__ __align__(128) char Asm[2][16384];
    __shared__ __align__(128) char Bsm[2][8192];

    int tid = threadIdx.x;
    int lane = tid & 31, wid = tid >> 5;
    int wm = wid & 3, wn = wid >> 2;
    int row0 = blockIdx.y * 128;
    int col0 = blockIdx.x * 64;

    uint32_t aBase = smem_u32(Asm);
    uint32_t bBase = smem_u32(Bsm);

    float acc[2][4][4];
#pragma unroll
    for (int i = 0; i < 2; i++)
#pragma unroll
        for (int j = 0; j < 4; j++)
#pragma unroll
            for (int q = 0; q < 4; q++) acc[i][j][q] = 0.0f;

    auto issue = [&](int st, int kt) {
#pragma unroll
        for (int i = 0; i < 6; i++) {
            int idx = tid + i * 256;
            if (idx < 1024) {
                int row = idx >> 3, c16 = idx & 7;
                const __nv_bfloat16* s = (c16 < 4) ? Ahi : Alo;
                const void* src = s + (size_t)(row0 + row) * DIM + kt * 32 + (c16 & 3) * 8;
                cp16(aBase + st * 16384 + SWZ((uint32_t)(row * 128 + c16 * 16)), src);
            } else {
                int j = idx - 1024;
                int row = j >> 3, c16 = j & 7;
                const __nv_bfloat16* s = (c16 < 4) ? Bhi : Blo;
                const void* src = s + (size_t)(col0 + row) * DIM + kt * 32 + (c16 & 3) * 8;
                cp16(bBase + st * 8192 + SWZ((uint32_t)(row * 128 + c16 * 16)), src);
            }
        }
    };

    issue(0, 0);
    asm volatile("cp.async.commit_group;" ::: "memory");

    for (int kt = 0; kt < 24; kt++) {
        int st = kt & 1;
        if (kt < 23) {
            issue(st ^ 1, kt + 1);
            asm volatile("cp.async.commit_group;" ::: "memory");
            asm volatile("cp.async.wait_group 1;" ::: "memory");
        } else {
            asm volatile("cp.async.wait_group 0;" ::: "memory");
        }
        __syncthreads();

        uint32_t aTile = aBase + st * 16384;
        uint32_t bTile = bBase + st * 8192;

        uint32_t af[4][2][4];
        int arow = wm * 32 + (lane & 15);
        int abyte = ((lane >> 4) & 1) * 16;
#pragma unroll
        for (int s2 = 0; s2 < 4; s2++)
#pragma unroll
            for (int mf = 0; mf < 2; mf++)
                ldsm4(af[s2][mf], aTile + SWZ((uint32_t)((arow + mf * 16) * 128 + abyte + s2 * 32)));

        const int alist[4][2] = {{0, 2}, {1, 3}, {0, -1}, {1, -1}};
        int brow_base = wn * 32 + ((lane >> 4) & 1) * 8 + (lane & 7);
        int bbyte = ((lane >> 3) & 1) * 16;
#pragma unroll
        for (int s2 = 0; s2 < 4; s2++) {
            uint32_t bfr[2][4];
#pragma unroll
            for (int np = 0; np < 2; np++)
                ldsm4(bfr[np], bTile + SWZ((uint32_t)((brow_base + np * 16) * 128 + bbyte + s2 * 32)));
#pragma unroll
            for (int q = 0; q < 2; q++) {
                int a = alist[s2][q];
                if (a >= 0) {
#pragma unroll
                    for (int mf = 0; mf < 2; mf++)
#pragma unroll
                        for (int np = 0; np < 2; np++) {
                            mma16816(acc[mf][np * 2 + 0], af[a][mf], &bfr[np][0]);
                            mma16816(acc[mf][np * 2 + 1], af[a][mf], &bfr[np][2]);
                        }
                }
            }
        }
        __syncthreads();
    }

#pragma unroll
    for (int mf = 0; mf < 2; mf++) {
#pragma unroll
        for (int nf = 0; nf < 4; nf++) {
            int cg = col0 + wn * 32 + nf * 8 + 2 * (lane & 3);
            float b0 = bias[cg], b1 = bias[cg + 1];
            int hi = cg >> 1;
#pragma unroll
            for (int half = 0; half < 2; half++) {
                int row = row0 + wm * 32 + mf * 16 + (lane >> 2) + half * 8;
                float v0 = acc[mf][nf][half * 2 + 0] + b0;
                float v1 = acc[mf][nf][half * 2 + 1] + b1;
                if (doRope) {
                    int s = row & (SQ - 1);
                    float cv = g_cos[s * HALF + hi];
                    float sv = g_sin[s * HALF + hi];
                    float r1 = v0 * cv - v1 * sv;
                    float r2 = v0 * sv + v1 * cv;
                    v0 = r1; v1 = r2;
                }
                *(float2*)&C[(size_t)row * DIM + cg] = make_float2(v0, v1);
            }
        }
    }
}

__global__ void __launch_bounds__(256) hgemm_qkv_kernel(
    const float* __restrict__ bq, const float* __restrict__ bk, const float* __restrict__ bv)
{
    int z = blockIdx.z;
    const float* b = (z == 0) ? bq : ((z == 1) ? bk : bv);
    float* C = (z == 0) ? g_Q : ((z == 1) ? g_K : g_V);
    size_t wb = (size_t)z * DIM * DIM;
    hgemm_core(g_Xhi, g_Xlo, g_Wthi + wb, g_Wtlo + wb, b, C, z < 2);
}

__global__ void __launch_bounds__(256) hgemm_out_kernel(
    const float* __restrict__ bo, float* __restrict__ out)
{
    size_t wb = (size_t)3 * DIM * DIM;
    hgemm_core(g_Ahi, g_Alo, g_Wthi + wb, g_Wtlo + wb, bo, out, false);
}

// ---------------- HMMA flash attention ----------------
// 8 warps: wm=wid&3 (rows 16wm..+16), wn=wid>>2 (S-cols 32wn..+32).
// smem: Khi 0 | Klo 8192 | Vhi 16384 | Vlo 24576 | red 32768 (2x2x64 f32)
// QK: hh+hl+lh; PV: PhiVhi + PhiVlo + PloVhi. Q prescaled by 0.125 at split.
__global__ void __launch_bounds__(256) attn_kernel() {
    __shared__ __align__(128) char sBuf[33792];
    float* sRed = (float*)(sBuf + 32768);

    int tid = threadIdx.x;
    int lane = tid & 31, wid = tid >> 5;
    int wm = wid & 3, wn = wid >> 2;
    int qt = (SQ / 64 - 1) - blockIdx.x;   // heavy tiles first
    int bh = blockIdx.y;
    int b = bh / NH, h = bh - b * NH;
    int qrow0 = qt * 64;

    uint32_t base = smem_u32(sBuf);

    // ---- stage Q tile (hi at 0, lo at 8192), extract A-frags ----
#pragma unroll
    for (int i = 0; i < 2; i++) {
        int idx = tid + i * 256;          // 0..511
        int row = idx >> 3, c16 = idx & 7;
        size_t goff = (size_t)(b * SQ + qrow0 + row) * DIM + h * HDIM + c16 * 8;
        cp16(base + SWZ((uint32_t)(row * 128 + c16 * 16)), g_Qhi + goff);
        cp16(base + 8192 + SWZ((uint32_t)(row * 128 + c16 * 16)), g_Qlo + goff);
    }
    asm volatile("cp.async.commit_group;" ::: "memory");
    asm volatile("cp.async.wait_group 0;" ::: "memory");
    __syncthreads();

    uint32_t qf[2][4][4];
    {
        int arow = wm * 16 + (lane & 15);
        int abyte = ((lane >> 4) & 1) * 16;
#pragma unroll
        for (int hl = 0; hl < 2; hl++)
#pragma unroll
            for (int s2 = 0; s2 < 4; s2++)
                ldsm4(qf[hl][s2], base + hl * 8192 + SWZ((uint32_t)(arow * 128 + abyte + s2 * 32)));
    }
    __syncthreads();   // Q frags extracted before K/V overwrite

    float m[2] = {-1e30f, -1e30f}, l[2] = {0.0f, 0.0f};
    float o[8][4];
#pragma unroll
    for (int j = 0; j < 8; j++)
#pragma unroll
        for (int q = 0; q < 4; q++) o[j][q] = 0.0f;

    int brow = ((lane >> 4) & 1) * 8 + (lane & 7);
    int bbyte = ((lane >> 3) & 1) * 16;
    int r0 = wm * 16 + (lane >> 2);

    for (int kt = 0; kt <= qt; kt++) {
        int krow0 = kt * 64;
        // ---- load K hi/lo + Vt hi/lo tiles ----
#pragma unroll
        for (int i = 0; i < 8; i++) {
            int idx = tid + i * 256;      // 0..2047
            int sel = idx >> 9, j = idx & 511;
            int row = j >> 3, c16 = j & 7;
            uint32_t dst = base + sel * 8192 + SWZ((uint32_t)(row * 128 + c16 * 16));
            const void* src;
            if (sel == 0)      src = g_Khi  + (size_t)(b * SQ + krow0 + row) * DIM + h * HDIM + c16 * 8;
            else if (sel == 1) src = g_Klo  + (size_t)(b * SQ + krow0 + row) * DIM + h * HDIM + c16 * 8;
            else if (sel == 2) src = g_Vthi + (size_t)(b * DIM + h * HDIM + row) * SQ + krow0 + c16 * 8;
            else               src = g_Vtlo + (size_t)(b * DIM + h * HDIM + row) * SQ + krow0 + c16 * 8;
            cp16(dst, src);
        }
        asm volatile("cp.async.commit_group;" ::: "memory");
        asm volatile("cp.async.wait_group 0;" ::: "memory");
        __syncthreads();

        // ---- QK^T: S = Qhi*Khi + Qhi*Klo + Qlo*Khi ----
        float sa[4][4];
#pragma unroll
        for (int nf = 0; nf < 4; nf++)
#pragma unroll
            for (int q = 0; q < 4; q++) sa[nf][q] = 0.0f;

#pragma unroll
        for (int s2 = 0; s2 < 4; s2++) {
            uint32_t kh[2][4], kl[2][4];
#pragma unroll
            for (int np = 0; np < 2; np++) {
                uint32_t roff = (uint32_t)((wn * 32 + np * 16 + brow) * 128 + bbyte + s2 * 32);
                ldsm4(kh[np], base + SWZ(roff));
                ldsm4(kl[np], base + 8192 + SWZ(roff));
            }
#pragma unroll
            for (int np = 0; np < 2; np++) {
                mma16816(sa[np * 2 + 0], qf[0][s2], &kh[np][0]);
                mma16816(sa[np * 2 + 1], qf[0][s2], &kh[np][2]);
                mma16816(sa[np * 2 + 0], qf[0][s2], &kl[np][0]);
                mma16816(sa[np * 2 + 1], qf[0][s2], &kl[np][2]);
                mma16816(sa[np * 2 + 0], qf[1][s2], &kh[np][0]);
                mma16816(sa[np * 2 + 1], qf[1][s2], &kh[np][2]);
            }
        }

        // ---- causal mask (diagonal tile only) ----
        if (kt == qt) {
#pragma unroll
            for (int nf = 0; nf < 4; nf++) {
                int col = wn * 32 + nf * 8 + 2 * (lane & 3);
                if (col     > r0)     sa[nf][0] = -1e30f;
                if (col + 1 > r0)     sa[nf][1] = -1e30f;
                if (col     > r0 + 8) sa[nf][2] = -1e30f;
                if (col + 1 > r0 + 8) sa[nf][3] = -1e30f;
            }
        }

        // ---- row max (intra-quad shuffles + cross-wn smem) ----
        float vm0 = fmaxf(fmaxf(sa[0][0], sa[0][1]), fmaxf(sa[1][0], sa[1][1]));
        vm0 = fmaxf(vm0, fmaxf(fmaxf(sa[2][0], sa[2][1]), fmaxf(sa[3][0], sa[3][1])));
        float vm1 = fmaxf(fmaxf(sa[0][2], sa[0][3]), fmaxf(sa[1][2], sa[1][3]));
        vm1 = fmaxf(vm1, fmaxf(fmaxf(sa[2][2], sa[2][3]), fmaxf(sa[3][2], sa[3][3])));
#pragma unroll
        for (int ofs = 1; ofs <= 2; ofs <<= 1) {
            vm0 = fmaxf(vm0, __shfl_xor_sync(0xffffffffu, vm0, ofs));
            vm1 = fmaxf(vm1, __shfl_xor_sync(0xffffffffu, vm1, ofs));
        }
        if ((lane & 3) == 0) {
            sRed[wn * 64 + r0] = vm0;
            sRed[wn * 64 + r0 + 8] = vm1;
        }
        __syncthreads();
        float mn0 = fmaxf(m[0], fmaxf(vm0, sRed[(wn ^ 1) * 64 + r0]));
        float mn1 = fmaxf(m[1], fmaxf(vm1, sRed[(wn ^ 1) * 64 + r0 + 8]));
        float sc0 = __expf(m[0] - mn0);
        float sc1 = __expf(m[1] - mn1);

        // ---- exp + row sums ----
        float p[4][4];
        float vs0 = 0.0f, vs1 = 0.0f;
#pragma unroll
        for (int nf = 0; nf < 4; nf++) {
            p[nf][0] = __expf(sa[nf][0] - mn0);
            p[nf][1] = __expf(sa[nf][1] - mn0);
            p[nf][2] = __expf(sa[nf][2] - mn1);
            p[nf][3] = __expf(sa[nf][3] - mn1);
            vs0 += p[nf][0] + p[nf][1];
            vs1 += p[nf][2] + p[nf][3];
        }
#pragma unroll
        for (int ofs = 1; ofs <= 2; ofs <<= 1) {
            vs0 += __shfl_xor_sync(0xffffffffu, vs0, ofs);
            vs1 += __shfl_xor_sync(0xffffffffu, vs1, ofs);
        }
        if ((lane & 3) == 0) {
            sRed[128 + wn * 64 + r0] = vs0;
            sRed[128 + wn * 64 + r0 + 8] = vs1;
        }
        __syncthreads();
        l[0] = l[0] * sc0 + vs0 + sRed[128 + (wn ^ 1) * 64 + r0];
        l[1] = l[1] * sc1 + vs1 + sRed[128 + (wn ^ 1) * 64 + r0 + 8];
        m[0] = mn0; m[1] = mn1;

        // ---- rescale O ----
#pragma unroll
        for (int j = 0; j < 8; j++) {
            o[j][0] *= sc0; o[j][1] *= sc0;
            o[j][2] *= sc1; o[j][3] *= sc1;
        }

        // ---- P -> bf16 hi/lo A-frags (C->A register identity) ----
        uint32_t phi[2][4], plo[2][4];
#pragma unroll
        for (int mm = 0; mm < 2; mm++) {
            const float* pn0 = p[2 * mm];
            const float* pn1 = p[2 * mm + 1];
            phi[mm][0] = cvtpack(pn0[1], pn0[0]);
            phi[mm][1] = cvtpack(pn0[3], pn0[2]);
            phi[mm][2] = cvtpack(pn1[1], pn1[0]);
            phi[mm][3] = cvtpack(pn1[3], pn1[2]);
#pragma unroll
            for (int q = 0; q < 4; q++) {
                const float* pp = (q < 2) ? pn0 : pn1;
                int e = (q & 1) * 2;
                uint32_t ph = phi[mm][q];
                float h0 = __uint_as_float(ph << 16);
                float h1 = __uint_as_float(ph & 0xffff0000u);
                plo[mm][q] = cvtpack(pp[e + 1] - h1, pp[e + 0] - h0);
            }
        }

        // ---- PV: O += Phi*Vhi + Phi*Vlo + Plo*Vhi ----
#pragma unroll
        for (int mm = 0; mm < 2; mm++) {
#pragma unroll
            for (int np = 0; np < 4; np++) {
                uint32_t roff = (uint32_t)((np * 16 + brow) * 128 + wn * 64 + mm * 32 + bbyte);
                uint32_t vh[4], vl[4];
                ldsm4(vh, base + 16384 + SWZ(roff));
                ldsm4(vl, base + 24576 + SWZ(roff));
                mma16816(o[np * 2 + 0], phi[mm], &vh[0]);
                mma16816(o[np * 2 + 1], phi[mm], &vh[2]);
                mma16816(o[np * 2 + 0], phi[mm], &vl[0]);
                mma16816(o[np * 2 + 1], phi[mm], &vl[2]);
                mma16816(o[np * 2 + 0], plo[mm], &vh[0]);
                mma16816(o[np * 2 + 1], plo[mm], &vh[2]);
            }
        }
        __syncthreads();   // reads done before next tile load / epilogue reuse
    }

    // ---- epilogue: cross-wn sum via smem, normalize, write ----
    float* sO = (float*)sBuf;   // 64 x 64 f32 = 16KB (reuses K region)
    int dbase = 2 * (lane & 3);
    if (wn == 1) {
#pragma unroll
        for (int j = 0; j < 8; j++) {
            int d = j * 8 + dbase;
            *(float2*)&sO[r0 * 64 + d] = make_float2(o[j][0], o[j][1]);
            *(float2*)&sO[(r0 + 8) * 64 + d] = make_float2(o[j][2], o[j][3]);
        }
    }
    __syncthreads();
    if (wn == 0) {
        float inv0 = 1.0f / l[0];
        float inv1 = 1.0f / l[1];
        size_t row0g = (size_t)(b * SQ + qrow0 + r0) * DIM + h * HDIM;
        size_t row1g = (size_t)(b * SQ + qrow0 + r0 + 8) * DIM + h * HDIM;
#pragma unroll
        for (int j = 0; j < 8; j++) {
            int d = j * 8 + dbase;
            float2 q0 = *(const float2*)&sO[r0 * 64 + d];
            float2 q1 = *(const float2*)&sO[(r0 + 8) * 64 + d];
            *(float2*)&g_A[row0g + d] = make_float2((o[j][0] + q0.x) * inv0, (o[j][1] + q0.y) * inv0);
            *(float2*)&g_A[row1g + d] = make_float2((o[j][2] + q1.x) * inv1, (o[j][3] + q1.y) * inv1);
        }
    }
}

// ---------------- launch ----------------
extern "C" void kernel_launch(void* const* d_in, const int* in_sizes, int n_in,
                              void* d_out, int out_size) {
    const float* X  = (const float*)d_in[0];
    const float* Wq = (const float*)d_in[1];
    const float* bq = (const float*)d_in[2];
    const float* Wk = (const float*)d_in[3];
    const float* bk = (const float*)d_in[4];
    const float* Wv = (const float*)d_in[5];
    const float* bv = (const float*)d_in[6];
    const float* Wo = (const float*)d_in[7];
    const float* bo = (const float*)d_in[8];
    float* out = (float*)d_out;

    int splitGrid = (MROWS * DIM / 4 + 255) / 256;
    rope_table_kernel<<<(SQ * HALF + 255) / 256, 256>>>();
    split_kernel<<<splitGrid, 256>>>(X, 0);
    wsplit_kernel<<<dim3(24, 24, 4), dim3(32, 8)>>>(Wq, Wk, Wv, Wo);
    hgemm_qkv_kernel<<<dim3(12, 64, 3), 256>>>(bq, bk, bv);
    split_kernel<<<splitGrid, 256>>>(X, 2);   // Q -> Qhi/Qlo (x0.125)
    split_kernel<<<splitGrid, 256>>>(X, 3);   // K -> Khi/Klo
    vtsplit_kernel<<<dim3(64, 24, 4), dim3(32, 8)>>>();
    attn_kernel<<<dim3(32, 48), 256>>>();
    split_kernel<<<splitGrid, 256>>>(X, 1);   // A -> Ahi/Alo
    hgemm_out_kernel<<<dim3(12, 64), 256>>>(bo, out);
}